// round 7
// baseline (speedup 1.0000x reference)
#include <cuda_runtime.h>
#include <cuda_bf16.h>
#include <cstdint>

#define D 256
#define MAXM 100096   // >= N, multiple of 128
#define MAXE 1700000
#define SCANB 1024
#define MAXSB 128

// ---------------- scratch (device globals; no allocations) ----------------
__device__ float g_t[(size_t)MAXM * D];   // aggregated features (GEMM-a input)
__device__ float g_u[(size_t)MAXM * D];   // GEMM-a output
__device__ float g_hbuf[(size_t)MAXM * D];// conv1 output
__device__ float g_sum[D];
__device__ float g_sumsq[D];
__device__ float g_scale[D];
__device__ float g_shift[D];
// weights pre-converted to bf16 hi/lo: 4 matrices of 256x256
__device__ __nv_bfloat16 g_wh[4][D * D];
__device__ __nv_bfloat16 g_wl[4][D * D];
// CSR scratch
__device__ int g_deg[MAXM];
__device__ int g_cursor[MAXM];
__device__ int g_rowptr[MAXM + 1];
__device__ int g_col[MAXE];
__device__ int g_bsum[MAXSB];

// ---------------- BN helpers ----------------
__global__ void zero_stats_kernel() {
    g_sum[threadIdx.x] = 0.f;
    g_sumsq[threadIdx.x] = 0.f;
}

__global__ void stats_kernel(const float* __restrict__ X, int M) {
    int c = threadIdx.x;
    long long rows = (M + gridDim.x - 1) / gridDim.x;
    long long r0 = (long long)blockIdx.x * rows;
    long long r1 = r0 + rows;
    if (r1 > M) r1 = M;
    float s = 0.f, q = 0.f;
    for (long long r = r0; r < r1; r++) {
        float v = X[r * D + c];
        s += v;
        q += v * v;
    }
    if (r1 > r0) {
        atomicAdd(&g_sum[c], s);
        atomicAdd(&g_sumsq[c], q);
    }
}

__global__ void finalize_stats_kernel(const float* __restrict__ gamma,
                                      const float* __restrict__ beta, int M) {
    int c = threadIdx.x;
    float invM = 1.f / (float)M;
    float mu = g_sum[c] * invM;
    float var = g_sumsq[c] * invM - mu * mu;
    float sc = gamma[c] * rsqrtf(var + 1e-5f);
    g_scale[c] = sc;
    g_shift[c] = beta[c] - mu * sc;
}

// ---------------- weight pre-conversion (bf16 hi/lo split) ----------------
__global__ void convert_w_kernel(const float* __restrict__ W,
                                 __nv_bfloat16* __restrict__ Wh,
                                 __nv_bfloat16* __restrict__ Wl) {
    int i = blockIdx.x * blockDim.x + threadIdx.x;  // over D*D/2 pairs
    float2 v = ((const float2*)W)[i];
    __nv_bfloat162 hh = __floats2bfloat162_rn(v.x, v.y);
    float2 f = __bfloat1622float2(hh);
    __nv_bfloat162 ll = __floats2bfloat162_rn(v.x - f.x, v.y - f.y);
    ((__nv_bfloat162*)Wh)[i] = hh;
    ((__nv_bfloat162*)Wl)[i] = ll;
}

// ---------------- CSR build ----------------
__global__ void zero_deg_kernel(int M) {
    int i = blockIdx.x * blockDim.x + threadIdx.x;
    if (i < M) {
        g_deg[i] = 0;
        g_cursor[i] = 0;
    }
}

__global__ void hist_kernel(const int* __restrict__ dstIdx, int E) {
    int e = blockIdx.x * blockDim.x + threadIdx.x;
    if (e < E) atomicAdd(&g_deg[dstIdx[e]], 1);
}

__global__ void scan_block_kernel(int M) {
    __shared__ int sh[SCANB];
    int i = blockIdx.x * SCANB + threadIdx.x;
    int v = (i < M) ? g_deg[i] : 0;
    sh[threadIdx.x] = v;
    __syncthreads();
    for (int off = 1; off < SCANB; off <<= 1) {
        int t = (threadIdx.x >= off) ? sh[threadIdx.x - off] : 0;
        __syncthreads();
        sh[threadIdx.x] += t;
        __syncthreads();
    }
    if (i < M) g_rowptr[i] = sh[threadIdx.x] - v;
    if (threadIdx.x == SCANB - 1) g_bsum[blockIdx.x] = sh[SCANB - 1];
}

__global__ void scan_bsum_kernel(int nb) {
    if (threadIdx.x == 0) {
        int run = 0;
        for (int i = 0; i < nb; i++) {
            int v = g_bsum[i];
            g_bsum[i] = run;
            run += v;
        }
    }
}

__global__ void scan_add_kernel(int M, int E) {
    int i = blockIdx.x * SCANB + threadIdx.x;
    if (i < M) g_rowptr[i] += g_bsum[blockIdx.x];
    if (i == 0) g_rowptr[M] = E;
}

__global__ void fill_kernel(const int* __restrict__ srcIdx,
                            const int* __restrict__ dstIdx, int E) {
    int e = blockIdx.x * blockDim.x + threadIdx.x;
    if (e >= E) return;
    int d = dstIdx[e];
    int pos = g_rowptr[d] + atomicAdd(&g_cursor[d], 1);
    g_col[pos] = srcIdx[e];
}

// ---------------- CSR aggregation ----------------
// BN_FOLD=1: out = scale*(x_i + Σ x_j) + (1+deg)*shift  (BN linearity)
template <int BN_FOLD>
__global__ void agg_csr_kernel(const float* __restrict__ feat,
                               float* __restrict__ out, int M) {
    int node = blockIdx.x * 4 + (threadIdx.x >> 6);
    if (node >= M) return;
    int lane = threadIdx.x & 63;
    int e0 = __ldg(&g_rowptr[node]);
    int e1 = __ldg(&g_rowptr[node + 1]);
    const float4* base = (const float4*)feat;
    float4 acc = base[(size_t)node * 64 + lane];  // self term
    int e = e0;
    for (; e + 4 <= e1; e += 4) {
        int s0 = __ldg(&g_col[e + 0]);
        int s1 = __ldg(&g_col[e + 1]);
        int s2 = __ldg(&g_col[e + 2]);
        int s3 = __ldg(&g_col[e + 3]);
        float4 v0 = base[(size_t)s0 * 64 + lane];
        float4 v1 = base[(size_t)s1 * 64 + lane];
        float4 v2 = base[(size_t)s2 * 64 + lane];
        float4 v3 = base[(size_t)s3 * 64 + lane];
        acc.x += (v0.x + v1.x) + (v2.x + v3.x);
        acc.y += (v0.y + v1.y) + (v2.y + v3.y);
        acc.z += (v0.z + v1.z) + (v2.z + v3.z);
        acc.w += (v0.w + v1.w) + (v2.w + v3.w);
    }
    for (; e < e1; e++) {
        int s = __ldg(&g_col[e]);
        float4 v = base[(size_t)s * 64 + lane];
        acc.x += v.x;
        acc.y += v.y;
        acc.z += v.z;
        acc.w += v.w;
    }
    if (BN_FOLD) {
        float4 s = ((const float4*)g_scale)[lane];
        float4 sh = ((const float4*)g_shift)[lane];
        float k = (float)(1 + (e1 - e0));
        acc.x = acc.x * s.x + k * sh.x;
        acc.y = acc.y * s.y + k * sh.y;
        acc.z = acc.z * s.z + k * sh.z;
        acc.w = acc.w * s.w + k * sh.w;
    }
    ((float4*)out)[(size_t)node * 64 + lane] = acc;
}

// ---------------- tensor-core GEMM (bf16x3 split, fp32 accum) ----------------
// BN_IN: apply relu(A*scale+shift) when loading A (channel-wise over k)
// STATS: accumulate column sum/sumsq of output into g_sum/g_sumsq
// RELU : relu on output
#define BK 32
#define AS 40    // As row stride (elements)
#define BS 136   // Bs row stride (elements)

template <int BN_IN, int STATS, int RELU>
__global__ __launch_bounds__(256, 1) void gemm_tc_kernel(
    const float* __restrict__ A, const __nv_bfloat16* __restrict__ Wh,
    const __nv_bfloat16* __restrict__ Wl, const float* __restrict__ bias,
    float* __restrict__ C, int M) {
    __shared__ __nv_bfloat16 As_h[128 * AS];
    __shared__ __nv_bfloat16 As_l[128 * AS];
    __shared__ __nv_bfloat16 Bs_h[BK * BS];
    __shared__ __nv_bfloat16 Bs_l[BK * BS];

    int bm = blockIdx.x * 128;
    int bn = blockIdx.y * 128;
    int tid = threadIdx.x;
    int lane = tid & 31;
    int wid = tid >> 5;
    int warp_m = wid >> 2;   // 0..1
    int warp_n = wid & 3;    // 0..3

    float acc[4][4][4];
#pragma unroll
    for (int i = 0; i < 4; i++)
#pragma unroll
        for (int j = 0; j < 4; j++)
#pragma unroll
            for (int r = 0; r < 4; r++) acc[i][j][r] = 0.f;

    int a_row = tid >> 1;
    int a_kb = (tid & 1) * 16;
    bool a_valid = (bm + a_row) < M;

    uint32_t as_h_base = (uint32_t)__cvta_generic_to_shared(As_h);
    uint32_t as_l_base = (uint32_t)__cvta_generic_to_shared(As_l);
    uint32_t bs_h_base = (uint32_t)__cvta_generic_to_shared(Bs_h);
    uint32_t bs_l_base = (uint32_t)__cvta_generic_to_shared(Bs_l);

    for (int k0 = 0; k0 < D; k0 += BK) {
        // ---- load A tile (128 x BK), optional BN+relu, hi/lo split ----
        {
            const float* Ar = A + (size_t)(bm + a_row) * D + k0 + a_kb;
#pragma unroll
            for (int i = 0; i < 4; i++) {
                float4 v = a_valid ? *(const float4*)(Ar + i * 4)
                                   : make_float4(0.f, 0.f, 0.f, 0.f);
                if (BN_IN) {
                    float4 s = ((const float4*)g_scale)[((k0 + a_kb) >> 2) + i];
                    float4 sh = ((const float4*)g_shift)[((k0 + a_kb) >> 2) + i];
                    v.x = fmaxf(v.x * s.x + sh.x, 0.f);
                    v.y = fmaxf(v.y * s.y + sh.y, 0.f);
                    v.z = fmaxf(v.z * s.z + sh.z, 0.f);
                    v.w = fmaxf(v.w * s.w + sh.w, 0.f);
                }
                __nv_bfloat162 h01 = __floats2bfloat162_rn(v.x, v.y);
                __nv_bfloat162 h23 = __floats2bfloat162_rn(v.z, v.w);
                float2 f01 = __bfloat1622float2(h01);
                float2 f23 = __bfloat1622float2(h23);
                __nv_bfloat162 l01 = __floats2bfloat162_rn(v.x - f01.x, v.y - f01.y);
                __nv_bfloat162 l23 = __floats2bfloat162_rn(v.z - f23.x, v.w - f23.y);
                int off = a_row * AS + a_kb + i * 4;
                *(__nv_bfloat162*)&As_h[off] = h01;
                *(__nv_bfloat162*)&As_h[off + 2] = h23;
                *(__nv_bfloat162*)&As_l[off] = l01;
                *(__nv_bfloat162*)&As_l[off + 2] = l23;
            }
        }
        // ---- load B tile (BK x 128) directly as bf16 uint4 ----
        {
#pragma unroll
            for (int rep = 0; rep < 2; rep++) {
                int j = tid + rep * 256;     // 0..511
                int row = j >> 4;            // 0..31
                int c8 = (j & 15) * 8;       // 0..120
                size_t goff = (size_t)(k0 + row) * D + bn + c8;
                *(uint4*)&Bs_h[row * BS + c8] = *(const uint4*)(Wh + goff);
                *(uint4*)&Bs_l[row * BS + c8] = *(const uint4*)(Wl + goff);
            }
        }
        __syncthreads();

#pragma unroll
        for (int k16 = 0; k16 < BK; k16 += 16) {
            uint32_t ah[4][4];
            uint32_t al[4][4];
            uint32_t bh[4][2];
            uint32_t bl[4][2];
#pragma unroll
            for (int mi = 0; mi < 4; mi++) {
                int row = warp_m * 64 + mi * 16 + (lane & 15);
                int col = k16 + ((lane >> 4) << 3);
                uint32_t ad = as_h_base + (uint32_t)(row * AS + col) * 2;
                asm volatile("ldmatrix.sync.aligned.m8n8.x4.shared.b16 {%0,%1,%2,%3}, [%4];"
                             : "=r"(ah[mi][0]), "=r"(ah[mi][1]), "=r"(ah[mi][2]), "=r"(ah[mi][3])
                             : "r"(ad));
                uint32_t ad2 = as_l_base + (uint32_t)(row * AS + col) * 2;
                asm volatile("ldmatrix.sync.aligned.m8n8.x4.shared.b16 {%0,%1,%2,%3}, [%4];"
                             : "=r"(al[mi][0]), "=r"(al[mi][1]), "=r"(al[mi][2]), "=r"(al[mi][3])
                             : "r"(ad2));
            }
#pragma unroll
            for (int ni = 0; ni < 4; ni++) {
                int row = k16 + (lane & 15);
                int col = warp_n * 32 + ni * 8;
                uint32_t bd = bs_h_base + (uint32_t)(row * BS + col) * 2;
                asm volatile("ldmatrix.sync.aligned.m8n8.x2.trans.shared.b16 {%0,%1}, [%2];"
                             : "=r"(bh[ni][0]), "=r"(bh[ni][1]) : "r"(bd));
                uint32_t bd2 = bs_l_base + (uint32_t)(row * BS + col) * 2;
                asm volatile("ldmatrix.sync.aligned.m8n8.x2.trans.shared.b16 {%0,%1}, [%2];"
                             : "=r"(bl[ni][0]), "=r"(bl[ni][1]) : "r"(bd2));
            }
#pragma unroll
            for (int mi = 0; mi < 4; mi++) {
#pragma unroll
                for (int ni = 0; ni < 4; ni++) {
                    float* d = acc[mi][ni];
                    asm volatile(
                        "mma.sync.aligned.m16n8k16.row.col.f32.bf16.bf16.f32 "
                        "{%0,%1,%2,%3}, {%4,%5,%6,%7}, {%8,%9}, {%0,%1,%2,%3};"
                        : "+f"(d[0]), "+f"(d[1]), "+f"(d[2]), "+f"(d[3])
                        : "r"(ah[mi][0]), "r"(ah[mi][1]), "r"(ah[mi][2]), "r"(ah[mi][3]),
                          "r"(bh[ni][0]), "r"(bh[ni][1]));
                    asm volatile(
                        "mma.sync.aligned.m16n8k16.row.col.f32.bf16.bf16.f32 "
                        "{%0,%1,%2,%3}, {%4,%5,%6,%7}, {%8,%9}, {%0,%1,%2,%3};"
                        : "+f"(d[0]), "+f"(d[1]), "+f"(d[2]), "+f"(d[3])
                        : "r"(ah[mi][0]), "r"(ah[mi][1]), "r"(ah[mi][2]), "r"(ah[mi][3]),
                          "r"(bl[ni][0]), "r"(bl[ni][1]));
                    asm volatile(
                        "mma.sync.aligned.m16n8k16.row.col.f32.bf16.bf16.f32 "
                        "{%0,%1,%2,%3}, {%4,%5,%6,%7}, {%8,%9}, {%0,%1,%2,%3};"
                        : "+f"(d[0]), "+f"(d[1]), "+f"(d[2]), "+f"(d[3])
                        : "r"(al[mi][0]), "r"(al[mi][1]), "r"(al[mi][2]), "r"(al[mi][3]),
                          "r"(bh[ni][0]), "r"(bh[ni][1]));
                }
            }
        }
        __syncthreads();
    }

    // ---- epilogue: bias (+relu) + store (+ column stats) ----
    float csum[8], csq[8];
    if (STATS) {
#pragma unroll
        for (int i = 0; i < 8; i++) { csum[i] = 0.f; csq[i] = 0.f; }
    }
#pragma unroll
    for (int mi = 0; mi < 4; mi++) {
#pragma unroll
        for (int ni = 0; ni < 4; ni++) {
            int r0 = bm + warp_m * 64 + mi * 16 + (lane >> 2);
            int c0 = bn + warp_n * 32 + ni * 8 + (lane & 3) * 2;
            float b0 = bias[c0], b1 = bias[c0 + 1];
            float* d = acc[mi][ni];
            float2 v0 = make_float2(d[0] + b0, d[1] + b1);
            float2 v1 = make_float2(d[2] + b0, d[3] + b1);
            if (RELU) {
                v0.x = fmaxf(v0.x, 0.f); v0.y = fmaxf(v0.y, 0.f);
                v1.x = fmaxf(v1.x, 0.f); v1.y = fmaxf(v1.y, 0.f);
            }
            if (r0 < M) {
                *(float2*)&C[(size_t)r0 * D + c0] = v0;
                if (STATS) {
                    csum[ni * 2] += v0.x;     csq[ni * 2] += v0.x * v0.x;
                    csum[ni * 2 + 1] += v0.y; csq[ni * 2 + 1] += v0.y * v0.y;
                }
            }
            if (r0 + 8 < M) {
                *(float2*)&C[(size_t)(r0 + 8) * D + c0] = v1;
                if (STATS) {
                    csum[ni * 2] += v1.x;     csq[ni * 2] += v1.x * v1.x;
                    csum[ni * 2 + 1] += v1.y; csq[ni * 2 + 1] += v1.y * v1.y;
                }
            }
        }
    }
    if (STATS) {
        __shared__ float s_sum[128];
        __shared__ float s_sq[128];
        if (tid < 128) { s_sum[tid] = 0.f; s_sq[tid] = 0.f; }
        __syncthreads();
#pragma unroll
        for (int ni = 0; ni < 4; ni++) {
#pragma unroll
            for (int p = 0; p < 2; p++) {
                int cl = warp_n * 32 + ni * 8 + (lane & 3) * 2 + p;
                atomicAdd(&s_sum[cl], csum[ni * 2 + p]);
                atomicAdd(&s_sq[cl], csq[ni * 2 + p]);
            }
        }
        __syncthreads();
        if (tid < 128) {
            atomicAdd(&g_sum[bn + tid], s_sum[tid]);
            atomicAdd(&g_sumsq[bn + tid], s_sq[tid]);
        }
    }
}

// ---------------- driver ----------------
extern "C" void kernel_launch(void* const* d_in, const int* in_sizes, int n_in,
                              void* d_out, int out_size) {
    const float* x = (const float*)d_in[0];
    const int* ei = (const int*)d_in[1];   // int32 (JAX x64 disabled)
    const float* g0 = (const float*)d_in[2];
    const float* b0 = (const float*)d_in[3];
    const float* W1a = (const float*)d_in[4];
    const float* b1a = (const float*)d_in[5];
    const float* g1 = (const float*)d_in[6];
    const float* bt1 = (const float*)d_in[7];
    const float* W1b = (const float*)d_in[8];
    const float* b1b = (const float*)d_in[9];
    const float* W2a = (const float*)d_in[10];
    const float* b2a = (const float*)d_in[11];
    const float* g2 = (const float*)d_in[12];
    const float* bt2 = (const float*)d_in[13];
    const float* W2b = (const float*)d_in[14];
    const float* b2b = (const float*)d_in[15];
    float* out = (float*)d_out;

    int M = in_sizes[0] / D;
    int E = in_sizes[1] / 2;
    const int* srcI = ei;
    const int* dstI = ei + E;

    float *t, *u, *h;
    cudaGetSymbolAddress((void**)&t, g_t);
    cudaGetSymbolAddress((void**)&u, g_u);
    cudaGetSymbolAddress((void**)&h, g_hbuf);
    __nv_bfloat16 *wh, *wl;
    cudaGetSymbolAddress((void**)&wh, g_wh);
    cudaGetSymbolAddress((void**)&wl, g_wl);
    __nv_bfloat16* Wh[4] = {wh, wh + D * D, wh + 2 * D * D, wh + 3 * D * D};
    __nv_bfloat16* Wl[4] = {wl, wl + D * D, wl + 2 * D * D, wl + 3 * D * D};

    dim3 gemmGrid((M + 127) / 128, 2);
    int aggGrid = (M + 3) / 4;
    int nb = (M + SCANB - 1) / SCANB;
    int cwGrid = (D * D / 2) / 256;

    // ---- pre-convert weights (once per launch) ----
    convert_w_kernel<<<cwGrid, 256>>>(W1a, Wh[0], Wl[0]);
    convert_w_kernel<<<cwGrid, 256>>>(W1b, Wh[1], Wl[1]);
    convert_w_kernel<<<cwGrid, 256>>>(W2a, Wh[2], Wl[2]);
    convert_w_kernel<<<cwGrid, 256>>>(W2b, Wh[3], Wl[3]);

    // ---- build CSR once (reused by both convs) ----
    zero_deg_kernel<<<(M + 255) / 256, 256>>>(M);
    hist_kernel<<<(E + 255) / 256, 256>>>(dstI, E);
    scan_block_kernel<<<nb, SCANB>>>(M);
    scan_bsum_kernel<<<1, 32>>>(nb);
    scan_add_kernel<<<nb, SCANB>>>(M, E);
    fill_kernel<<<(E + 255) / 256, 256>>>(srcI, dstI, E);

    // ---- BN0 stats on x; agg with BN folded (linearity) ----
    zero_stats_kernel<<<1, 256>>>();
    stats_kernel<<<512, 256>>>(x, M);
    finalize_stats_kernel<<<1, 256>>>(g0, b0, M);
    agg_csr_kernel<1><<<aggGrid, 256>>>(x, t, M);                       // t = BN0-agg(x)

    // ---- conv1 ----
    zero_stats_kernel<<<1, 256>>>();
    gemm_tc_kernel<0, 1, 0><<<gemmGrid, 256>>>(t, Wh[0], Wl[0], b1a, u, M);  // u + stats
    finalize_stats_kernel<<<1, 256>>>(g1, bt1, M);
    gemm_tc_kernel<1, 0, 1><<<gemmGrid, 256>>>(u, Wh[1], Wl[1], b1b, h, M);  // h = relu(relu(BN(u))@W1b+b)

    // ---- conv2 ----
    agg_csr_kernel<0><<<aggGrid, 256>>>(h, t, M);                       // t = h + Σh
    zero_stats_kernel<<<1, 256>>>();
    gemm_tc_kernel<0, 1, 0><<<gemmGrid, 256>>>(t, Wh[2], Wl[2], b2a, u, M);
    finalize_stats_kernel<<<1, 256>>>(g2, bt2, M);
    gemm_tc_kernel<1, 0, 1><<<gemmGrid, 256>>>(u, Wh[3], Wl[3], b2b, out, M);
}

// round 8
// speedup vs baseline: 1.1191x; 1.1191x over previous
#include <cuda_runtime.h>
#include <cuda_bf16.h>
#include <cstdint>

#define D 256
#define MAXM 100096   // >= N, multiple of 128
#define MAXE 1700000
#define SCANB 1024
#define MAXSB 128

// ---------------- scratch (device globals; no allocations) ----------------
__device__ float g_t[(size_t)MAXM * D];   // aggregated features (GEMM-a input)
__device__ float g_u[(size_t)MAXM * D];   // GEMM-a output
__device__ float g_hbuf[(size_t)MAXM * D];// conv1 output
__device__ float g_sum[D];
__device__ float g_sumsq[D];
__device__ float g_scale[D];
__device__ float g_shift[D];
// weights pre-converted to bf16 hi/lo: 4 matrices of 256x256
__device__ __nv_bfloat16 g_wh[4][D * D];
__device__ __nv_bfloat16 g_wl[4][D * D];
// CSR scratch
__device__ int g_deg[MAXM];
__device__ int g_cursor[MAXM];
__device__ int g_rowptr[MAXM + 1];
__device__ int g_col[MAXE];
__device__ int g_bsum[MAXSB];

// ---------------- BN helpers ----------------
__global__ void zero_stats_kernel() {
    g_sum[threadIdx.x] = 0.f;
    g_sumsq[threadIdx.x] = 0.f;
}

// per-column sum & sumsq; block = 256 threads (one per column), 4-row unroll
__global__ void stats_kernel(const float* __restrict__ X, int M) {
    int c = threadIdx.x;
    int rows = (M + gridDim.x - 1) / gridDim.x;
    int r0 = blockIdx.x * rows;
    int r1 = r0 + rows;
    if (r1 > M) r1 = M;
    float s = 0.f, q = 0.f;
    int r = r0;
    for (; r + 4 <= r1; r += 4) {
        float v0 = X[(size_t)(r + 0) * D + c];
        float v1 = X[(size_t)(r + 1) * D + c];
        float v2 = X[(size_t)(r + 2) * D + c];
        float v3 = X[(size_t)(r + 3) * D + c];
        s += (v0 + v1) + (v2 + v3);
        q += (v0 * v0 + v1 * v1) + (v2 * v2 + v3 * v3);
    }
    for (; r < r1; r++) {
        float v = X[(size_t)r * D + c];
        s += v;
        q += v * v;
    }
    if (r1 > r0) {
        atomicAdd(&g_sum[c], s);
        atomicAdd(&g_sumsq[c], q);
    }
}

__global__ void finalize_stats_kernel(const float* __restrict__ gamma,
                                      const float* __restrict__ beta, int M) {
    int c = threadIdx.x;
    float invM = 1.f / (float)M;
    float mu = g_sum[c] * invM;
    float var = g_sumsq[c] * invM - mu * mu;
    float sc = gamma[c] * rsqrtf(var + 1e-5f);
    g_scale[c] = sc;
    g_shift[c] = beta[c] - mu * sc;
}

// ---------------- weight pre-conversion (bf16 hi/lo split) ----------------
__global__ void convert_w_kernel(const float* __restrict__ W,
                                 __nv_bfloat16* __restrict__ Wh,
                                 __nv_bfloat16* __restrict__ Wl) {
    int i = blockIdx.x * blockDim.x + threadIdx.x;  // over D*D/2 pairs
    float2 v = ((const float2*)W)[i];
    __nv_bfloat162 hh = __floats2bfloat162_rn(v.x, v.y);
    float2 f = __bfloat1622float2(hh);
    __nv_bfloat162 ll = __floats2bfloat162_rn(v.x - f.x, v.y - f.y);
    ((__nv_bfloat162*)Wh)[i] = hh;
    ((__nv_bfloat162*)Wl)[i] = ll;
}

// ---------------- CSR build ----------------
__global__ void zero_deg_kernel(int M) {
    int i = blockIdx.x * blockDim.x + threadIdx.x;
    if (i < M) {
        g_deg[i] = 0;
        g_cursor[i] = 0;
    }
}

__global__ void hist_kernel(const int* __restrict__ dstIdx, int E) {
    int e = blockIdx.x * blockDim.x + threadIdx.x;
    if (e < E) atomicAdd(&g_deg[dstIdx[e]], 1);
}

__global__ void scan_block_kernel(int M) {
    __shared__ int sh[SCANB];
    int i = blockIdx.x * SCANB + threadIdx.x;
    int v = (i < M) ? g_deg[i] : 0;
    sh[threadIdx.x] = v;
    __syncthreads();
    for (int off = 1; off < SCANB; off <<= 1) {
        int t = (threadIdx.x >= off) ? sh[threadIdx.x - off] : 0;
        __syncthreads();
        sh[threadIdx.x] += t;
        __syncthreads();
    }
    if (i < M) g_rowptr[i] = sh[threadIdx.x] - v;
    if (threadIdx.x == SCANB - 1) g_bsum[blockIdx.x] = sh[SCANB - 1];
}

__global__ void scan_bsum_kernel(int nb) {
    if (threadIdx.x == 0) {
        int run = 0;
        for (int i = 0; i < nb; i++) {
            int v = g_bsum[i];
            g_bsum[i] = run;
            run += v;
        }
    }
}

__global__ void scan_add_kernel(int M, int E) {
    int i = blockIdx.x * SCANB + threadIdx.x;
    if (i < M) g_rowptr[i] += g_bsum[blockIdx.x];
    if (i == 0) g_rowptr[M] = E;
}

__global__ void fill_kernel(const int* __restrict__ srcIdx,
                            const int* __restrict__ dstIdx, int E) {
    int e = blockIdx.x * blockDim.x + threadIdx.x;
    if (e >= E) return;
    int d = dstIdx[e];
    int pos = g_rowptr[d] + atomicAdd(&g_cursor[d], 1);
    g_col[pos] = srcIdx[e];
}

// ---------------- CSR aggregation ----------------
// BN_FOLD=1: out = scale*(x_i + Σ x_j) + (1+deg)*shift  (BN linearity)
template <int BN_FOLD>
__global__ void agg_csr_kernel(const float* __restrict__ feat,
                               float* __restrict__ out, int M) {
    int node = blockIdx.x * 4 + (threadIdx.x >> 6);
    if (node >= M) return;
    int lane = threadIdx.x & 63;
    int e0 = __ldg(&g_rowptr[node]);
    int e1 = __ldg(&g_rowptr[node + 1]);
    const float4* base = (const float4*)feat;
    float4 acc = base[(size_t)node * 64 + lane];  // self term
    int e = e0;
    for (; e + 4 <= e1; e += 4) {
        int s0 = __ldg(&g_col[e + 0]);
        int s1 = __ldg(&g_col[e + 1]);
        int s2 = __ldg(&g_col[e + 2]);
        int s3 = __ldg(&g_col[e + 3]);
        float4 v0 = base[(size_t)s0 * 64 + lane];
        float4 v1 = base[(size_t)s1 * 64 + lane];
        float4 v2 = base[(size_t)s2 * 64 + lane];
        float4 v3 = base[(size_t)s3 * 64 + lane];
        acc.x += (v0.x + v1.x) + (v2.x + v3.x);
        acc.y += (v0.y + v1.y) + (v2.y + v3.y);
        acc.z += (v0.z + v1.z) + (v2.z + v3.z);
        acc.w += (v0.w + v1.w) + (v2.w + v3.w);
    }
    for (; e < e1; e++) {
        int s = __ldg(&g_col[e]);
        float4 v = base[(size_t)s * 64 + lane];
        acc.x += v.x;
        acc.y += v.y;
        acc.z += v.z;
        acc.w += v.w;
    }
    if (BN_FOLD) {
        float4 s = ((const float4*)g_scale)[lane];
        float4 sh = ((const float4*)g_shift)[lane];
        float k = (float)(1 + (e1 - e0));
        acc.x = acc.x * s.x + k * sh.x;
        acc.y = acc.y * s.y + k * sh.y;
        acc.z = acc.z * s.z + k * sh.z;
        acc.w = acc.w * s.w + k * sh.w;
    }
    ((float4*)out)[(size_t)node * 64 + lane] = acc;
}

// ---------------- tensor-core GEMM (bf16x3 split, fp32 accum) ----------------
// BN_IN: apply relu(A*scale+shift) when loading A (channel-wise over k)
// RELU : relu on output
#define BK 32
#define AS 40    // As row stride (elements)
#define BS 136   // Bs row stride (elements)

template <int BN_IN, int RELU>
__global__ __launch_bounds__(256, 1) void gemm_tc_kernel(
    const float* __restrict__ A, const __nv_bfloat16* __restrict__ Wh,
    const __nv_bfloat16* __restrict__ Wl, const float* __restrict__ bias,
    float* __restrict__ C, int M) {
    __shared__ __nv_bfloat16 As_h[128 * AS];
    __shared__ __nv_bfloat16 As_l[128 * AS];
    __shared__ __nv_bfloat16 Bs_h[BK * BS];
    __shared__ __nv_bfloat16 Bs_l[BK * BS];

    int bm = blockIdx.x * 128;
    int bn = blockIdx.y * 128;
    int tid = threadIdx.x;
    int lane = tid & 31;
    int wid = tid >> 5;
    int warp_m = wid >> 2;   // 0..1
    int warp_n = wid & 3;    // 0..3

    float acc[4][4][4];
#pragma unroll
    for (int i = 0; i < 4; i++)
#pragma unroll
        for (int j = 0; j < 4; j++)
#pragma unroll
            for (int r = 0; r < 4; r++) acc[i][j][r] = 0.f;

    int a_row = tid >> 1;
    int a_kb = (tid & 1) * 16;
    bool a_valid = (bm + a_row) < M;

    uint32_t as_h_base = (uint32_t)__cvta_generic_to_shared(As_h);
    uint32_t as_l_base = (uint32_t)__cvta_generic_to_shared(As_l);
    uint32_t bs_h_base = (uint32_t)__cvta_generic_to_shared(Bs_h);
    uint32_t bs_l_base = (uint32_t)__cvta_generic_to_shared(Bs_l);

    for (int k0 = 0; k0 < D; k0 += BK) {
        // ---- load A tile (128 x BK), optional BN+relu, hi/lo split ----
        {
            const float* Ar = A + (size_t)(bm + a_row) * D + k0 + a_kb;
#pragma unroll
            for (int i = 0; i < 4; i++) {
                float4 v = a_valid ? *(const float4*)(Ar + i * 4)
                                   : make_float4(0.f, 0.f, 0.f, 0.f);
                if (BN_IN) {
                    float4 s = ((const float4*)g_scale)[((k0 + a_kb) >> 2) + i];
                    float4 sh = ((const float4*)g_shift)[((k0 + a_kb) >> 2) + i];
                    v.x = fmaxf(v.x * s.x + sh.x, 0.f);
                    v.y = fmaxf(v.y * s.y + sh.y, 0.f);
                    v.z = fmaxf(v.z * s.z + sh.z, 0.f);
                    v.w = fmaxf(v.w * s.w + sh.w, 0.f);
                }
                __nv_bfloat162 h01 = __floats2bfloat162_rn(v.x, v.y);
                __nv_bfloat162 h23 = __floats2bfloat162_rn(v.z, v.w);
                float2 f01 = __bfloat1622float2(h01);
                float2 f23 = __bfloat1622float2(h23);
                __nv_bfloat162 l01 = __floats2bfloat162_rn(v.x - f01.x, v.y - f01.y);
                __nv_bfloat162 l23 = __floats2bfloat162_rn(v.z - f23.x, v.w - f23.y);
                int off = a_row * AS + a_kb + i * 4;
                *(__nv_bfloat162*)&As_h[off] = h01;
                *(__nv_bfloat162*)&As_h[off + 2] = h23;
                *(__nv_bfloat162*)&As_l[off] = l01;
                *(__nv_bfloat162*)&As_l[off + 2] = l23;
            }
        }
        // ---- load B tile (BK x 128) directly as bf16 uint4 ----
        {
#pragma unroll
            for (int rep = 0; rep < 2; rep++) {
                int j = tid + rep * 256;     // 0..511
                int row = j >> 4;            // 0..31
                int c8 = (j & 15) * 8;       // 0..120
                size_t goff = (size_t)(k0 + row) * D + bn + c8;
                *(uint4*)&Bs_h[row * BS + c8] = *(const uint4*)(Wh + goff);
                *(uint4*)&Bs_l[row * BS + c8] = *(const uint4*)(Wl + goff);
            }
        }
        __syncthreads();

#pragma unroll
        for (int k16 = 0; k16 < BK; k16 += 16) {
            uint32_t ah[4][4];
            uint32_t al[4][4];
            uint32_t bh[4][2];
            uint32_t bl[4][2];
#pragma unroll
            for (int mi = 0; mi < 4; mi++) {
                int row = warp_m * 64 + mi * 16 + (lane & 15);
                int col = k16 + ((lane >> 4) << 3);
                uint32_t ad = as_h_base + (uint32_t)(row * AS + col) * 2;
                asm volatile("ldmatrix.sync.aligned.m8n8.x4.shared.b16 {%0,%1,%2,%3}, [%4];"
                             : "=r"(ah[mi][0]), "=r"(ah[mi][1]), "=r"(ah[mi][2]), "=r"(ah[mi][3])
                             : "r"(ad));
                uint32_t ad2 = as_l_base + (uint32_t)(row * AS + col) * 2;
                asm volatile("ldmatrix.sync.aligned.m8n8.x4.shared.b16 {%0,%1,%2,%3}, [%4];"
                             : "=r"(al[mi][0]), "=r"(al[mi][1]), "=r"(al[mi][2]), "=r"(al[mi][3])
                             : "r"(ad2));
            }
#pragma unroll
            for (int ni = 0; ni < 4; ni++) {
                int row = k16 + (lane & 15);
                int col = warp_n * 32 + ni * 8;
                uint32_t bd = bs_h_base + (uint32_t)(row * BS + col) * 2;
                asm volatile("ldmatrix.sync.aligned.m8n8.x2.trans.shared.b16 {%0,%1}, [%2];"
                             : "=r"(bh[ni][0]), "=r"(bh[ni][1]) : "r"(bd));
                uint32_t bd2 = bs_l_base + (uint32_t)(row * BS + col) * 2;
                asm volatile("ldmatrix.sync.aligned.m8n8.x2.trans.shared.b16 {%0,%1}, [%2];"
                             : "=r"(bl[ni][0]), "=r"(bl[ni][1]) : "r"(bd2));
            }
#pragma unroll
            for (int mi = 0; mi < 4; mi++) {
#pragma unroll
                for (int ni = 0; ni < 4; ni++) {
                    float* d = acc[mi][ni];
                    asm volatile(
                        "mma.sync.aligned.m16n8k16.row.col.f32.bf16.bf16.f32 "
                        "{%0,%1,%2,%3}, {%4,%5,%6,%7}, {%8,%9}, {%0,%1,%2,%3};"
                        : "+f"(d[0]), "+f"(d[1]), "+f"(d[2]), "+f"(d[3])
                        : "r"(ah[mi][0]), "r"(ah[mi][1]), "r"(ah[mi][2]), "r"(ah[mi][3]),
                          "r"(bh[ni][0]), "r"(bh[ni][1]));
                    asm volatile(
                        "mma.sync.aligned.m16n8k16.row.col.f32.bf16.bf16.f32 "
                        "{%0,%1,%2,%3}, {%4,%5,%6,%7}, {%8,%9}, {%0,%1,%2,%3};"
                        : "+f"(d[0]), "+f"(d[1]), "+f"(d[2]), "+f"(d[3])
                        : "r"(ah[mi][0]), "r"(ah[mi][1]), "r"(ah[mi][2]), "r"(ah[mi][3]),
                          "r"(bl[ni][0]), "r"(bl[ni][1]));
                    asm volatile(
                        "mma.sync.aligned.m16n8k16.row.col.f32.bf16.bf16.f32 "
                        "{%0,%1,%2,%3}, {%4,%5,%6,%7}, {%8,%9}, {%0,%1,%2,%3};"
                        : "+f"(d[0]), "+f"(d[1]), "+f"(d[2]), "+f"(d[3])
                        : "r"(al[mi][0]), "r"(al[mi][1]), "r"(al[mi][2]), "r"(al[mi][3]),
                          "r"(bh[ni][0]), "r"(bh[ni][1]));
                }
            }
        }
        __syncthreads();
    }

    // ---- epilogue: bias (+relu) + store ----
#pragma unroll
    for (int mi = 0; mi < 4; mi++) {
#pragma unroll
        for (int ni = 0; ni < 4; ni++) {
            int r0 = bm + warp_m * 64 + mi * 16 + (lane >> 2);
            int c0 = bn + warp_n * 32 + ni * 8 + (lane & 3) * 2;
            float b0 = bias[c0], b1 = bias[c0 + 1];
            float* d = acc[mi][ni];
            float2 v0 = make_float2(d[0] + b0, d[1] + b1);
            float2 v1 = make_float2(d[2] + b0, d[3] + b1);
            if (RELU) {
                v0.x = fmaxf(v0.x, 0.f); v0.y = fmaxf(v0.y, 0.f);
                v1.x = fmaxf(v1.x, 0.f); v1.y = fmaxf(v1.y, 0.f);
            }
            if (r0 < M) *(float2*)&C[(size_t)r0 * D + c0] = v0;
            if (r0 + 8 < M) *(float2*)&C[(size_t)(r0 + 8) * D + c0] = v1;
        }
    }
}

// ---------------- driver ----------------
extern "C" void kernel_launch(void* const* d_in, const int* in_sizes, int n_in,
                              void* d_out, int out_size) {
    const float* x = (const float*)d_in[0];
    const int* ei = (const int*)d_in[1];   // int32 (JAX x64 disabled)
    const float* g0 = (const float*)d_in[2];
    const float* b0 = (const float*)d_in[3];
    const float* W1a = (const float*)d_in[4];
    const float* b1a = (const float*)d_in[5];
    const float* g1 = (const float*)d_in[6];
    const float* bt1 = (const float*)d_in[7];
    const float* W1b = (const float*)d_in[8];
    const float* b1b = (const float*)d_in[9];
    const float* W2a = (const float*)d_in[10];
    const float* b2a = (const float*)d_in[11];
    const float* g2 = (const float*)d_in[12];
    const float* bt2 = (const float*)d_in[13];
    const float* W2b = (const float*)d_in[14];
    const float* b2b = (const float*)d_in[15];
    float* out = (float*)d_out;

    int M = in_sizes[0] / D;
    int E = in_sizes[1] / 2;
    const int* srcI = ei;
    const int* dstI = ei + E;

    float *t, *u, *h;
    cudaGetSymbolAddress((void**)&t, g_t);
    cudaGetSymbolAddress((void**)&u, g_u);
    cudaGetSymbolAddress((void**)&h, g_hbuf);
    __nv_bfloat16 *wh, *wl;
    cudaGetSymbolAddress((void**)&wh, g_wh);
    cudaGetSymbolAddress((void**)&wl, g_wl);
    __nv_bfloat16* Wh[4] = {wh, wh + D * D, wh + 2 * D * D, wh + 3 * D * D};
    __nv_bfloat16* Wl[4] = {wl, wl + D * D, wl + 2 * D * D, wl + 3 * D * D};

    dim3 gemmGrid((M + 127) / 128, 2);
    int aggGrid = (M + 3) / 4;
    int nb = (M + SCANB - 1) / SCANB;
    int cwGrid = (D * D / 2) / 256;

    // ---- pre-convert weights (once per launch) ----
    convert_w_kernel<<<cwGrid, 256>>>(W1a, Wh[0], Wl[0]);
    convert_w_kernel<<<cwGrid, 256>>>(W1b, Wh[1], Wl[1]);
    convert_w_kernel<<<cwGrid, 256>>>(W2a, Wh[2], Wl[2]);
    convert_w_kernel<<<cwGrid, 256>>>(W2b, Wh[3], Wl[3]);

    // ---- build CSR once (reused by both convs) ----
    zero_deg_kernel<<<(M + 255) / 256, 256>>>(M);
    hist_kernel<<<(E + 255) / 256, 256>>>(dstI, E);
    scan_block_kernel<<<nb, SCANB>>>(M);
    scan_bsum_kernel<<<1, 32>>>(nb);
    scan_add_kernel<<<nb, SCANB>>>(M, E);
    fill_kernel<<<(E + 255) / 256, 256>>>(srcI, dstI, E);

    // ---- BN0 stats on x; agg with BN folded (linearity) ----
    zero_stats_kernel<<<1, 256>>>();
    stats_kernel<<<512, 256>>>(x, M);
    finalize_stats_kernel<<<1, 256>>>(g0, b0, M);
    agg_csr_kernel<1><<<aggGrid, 256>>>(x, t, M);                       // t = BN0-agg(x)

    // ---- conv1 ----
    gemm_tc_kernel<0, 0><<<gemmGrid, 256>>>(t, Wh[0], Wl[0], b1a, u, M);     // u = t@W1a+b
    zero_stats_kernel<<<1, 256>>>();
    stats_kernel<<<512, 256>>>(u, M);
    finalize_stats_kernel<<<1, 256>>>(g1, bt1, M);
    gemm_tc_kernel<1, 1><<<gemmGrid, 256>>>(u, Wh[1], Wl[1], b1b, h, M);     // h = relu(relu(BN(u))@W1b+b)

    // ---- conv2 ----
    agg_csr_kernel<0><<<aggGrid, 256>>>(h, t, M);                       // t = h + Σh
    gemm_tc_kernel<0, 0><<<gemmGrid, 256>>>(t, Wh[2], Wl[2], b2a, u, M);
    zero_stats_kernel<<<1, 256>>>();
    stats_kernel<<<512, 256>>>(u, M);
    finalize_stats_kernel<<<1, 256>>>(g2, bt2, M);
    gemm_tc_kernel<1, 1><<<gemmGrid, 256>>>(u, Wh[3], Wl[3], b2b, out, M);
}